// round 5
// baseline (speedup 1.0000x reference)
#include <cuda_runtime.h>
#include <cstdint>
#include <cstddef>

// GGNN: B=8, N=1024, H=64, E=2, NUM_STEPS=5
// s = adj @ G, G = [h@C_in0; h@C_in1; h@C_out0; h@C_out1] + d  (C = W_edge x W_gate folded)
// z = sigmoid(s + h@Wg3 + bg); h~ = tanh(s + (z*h)@Wg3 + bg); h = (1-z)h + z*h~

#define NSTEPS 5
#define BB 8
#define NN 1024

// ---------------- scratch (device globals; no allocations allowed) ----------------
__device__ float g_C[64 * 320];                    // [C_in0|C_in1|C_out0|C_out1|Wg3], tf32-rounded
__device__ float g_d[320];                         // folded biases (block 4 = 0)
__device__ float g_G[(size_t)BB * 4096 * 64];      // per-batch B operand of big GEMM (tf32-rounded)
__device__ float g_u[(size_t)BB * 1024 * 64];      // u = h @ Wg3
__device__ float g_h[(size_t)BB * 1024 * 64];      // hidden state (in-place updated)

// ---------------- helpers ----------------
__device__ __forceinline__ unsigned f2tf(float x) {
    unsigned r;
    asm("cvt.rna.tf32.f32 %0, %1;" : "=r"(r) : "f"(x));
    return r;
}
__device__ __forceinline__ float roundtf(float x) { return __uint_as_float(f2tf(x)); }

__device__ __forceinline__ void mma8(float c[4], unsigned a0, unsigned a1, unsigned a2, unsigned a3,
                                     unsigned b0, unsigned b1) {
    asm volatile(
        "mma.sync.aligned.m16n8k8.row.col.f32.tf32.tf32.f32 "
        "{%0,%1,%2,%3}, {%4,%5,%6,%7}, {%8,%9}, {%0,%1,%2,%3};"
        : "+f"(c[0]), "+f"(c[1]), "+f"(c[2]), "+f"(c[3])
        : "r"(a0), "r"(a1), "r"(a2), "r"(a3), "r"(b0), "r"(b1));
}

__device__ __forceinline__ void cpa16(float* smem_dst, const float* gsrc) {
    unsigned s = (unsigned)__cvta_generic_to_shared(smem_dst);
    asm volatile("cp.async.cg.shared.global [%0], [%1], 16;" :: "r"(s), "l"(gsrc) : "memory");
}
#define CP_COMMIT() asm volatile("cp.async.commit_group;" ::: "memory")
#define CP_WAIT1()  asm volatile("cp.async.wait_group 1;"  ::: "memory")

// Warp computes a 32x32 tile over K=64 from smem (A row-major [m][k], B [k][n]).
// lda=68, ldb=72 chosen so all fragment LDS are bank-conflict-free.
template <bool CVTA>
__device__ __forceinline__ void warptile64(const float* As, int lda, const float* Bs, int ldb,
                                           float acc[2][4][4], int mb, int nb, int g, int tg) {
#pragma unroll
    for (int kk = 0; kk < 8; kk++) {
        int k0 = kk * 8;
        unsigned a[2][4];
        unsigned b[4][2];
#pragma unroll
        for (int mf = 0; mf < 2; mf++) {
            const float* ap = As + (mb + mf * 16) * lda + k0;
            float x0 = ap[g * lda + tg];
            float x1 = ap[(g + 8) * lda + tg];
            float x2 = ap[g * lda + tg + 4];
            float x3 = ap[(g + 8) * lda + tg + 4];
            if (CVTA) {
                a[mf][0] = f2tf(x0); a[mf][1] = f2tf(x1);
                a[mf][2] = f2tf(x2); a[mf][3] = f2tf(x3);
            } else {
                a[mf][0] = __float_as_uint(x0); a[mf][1] = __float_as_uint(x1);
                a[mf][2] = __float_as_uint(x2); a[mf][3] = __float_as_uint(x3);
            }
        }
#pragma unroll
        for (int nf = 0; nf < 4; nf++) {
            const float* bp = Bs + k0 * ldb + nb + nf * 8 + g;
            b[nf][0] = __float_as_uint(bp[tg * ldb]);
            b[nf][1] = __float_as_uint(bp[(tg + 4) * ldb]);
        }
#pragma unroll
        for (int mf = 0; mf < 2; mf++)
#pragma unroll
            for (int nf = 0; nf < 4; nf++)
                mma8(acc[mf][nf], a[mf][0], a[mf][1], a[mf][2], a[mf][3], b[nf][0], b[nf][1]);
    }
}

// ---------------- kernel 0: fold W_edge/W_gate into C (64x320) and d (320) ----------------
__global__ void build_C_kernel(const float* __restrict__ We, const float* __restrict__ be,
                               const float* __restrict__ Wg) {
    int idx = blockIdx.x * 256 + threadIdx.x;
    if (idx < 64 * 320) {
        int hp = idx / 320, c = idx % 320;
        int blk = c / 64, j = c % 64;
        float acc;
        if (blk < 4) {
            acc = 0.f;
            int e = blk & 1;
            int go = (blk < 2) ? 0 : 64;
            for (int h = 0; h < 64; h++) acc += We[hp * 128 + 2 * h + e] * Wg[(go + h) * 64 + j];
        } else {
            acc = Wg[(128 + hp) * 64 + j];  // Wg3
        }
        g_C[hp * 320 + c] = roundtf(acc);
    }
    if (idx < 320) {
        int blk = idx / 64, j = idx % 64;
        float acc = 0.f;
        if (blk < 4) {
            int e = blk & 1;
            int go = (blk < 2) ? 0 : 64;
            for (int h = 0; h < 64; h++) acc += be[2 * h + e] * Wg[(go + h) * 64 + j];
        }
        g_d[idx] = acc;
    }
}

// ---------------- kernel 1: G build — h(1024x64) @ C(64x320) per batch ----------------
__global__ __launch_bounds__(128) void gbuild_kernel() {
    __shared__ __align__(16) float As[64 * 68];
    __shared__ __align__(16) float Cs[64 * 72];
    int tid = threadIdx.x;
    int mt = blockIdx.x, nt = blockIdx.y, b = blockIdx.z;
    int m0 = mt * 64;
    const float* hb = g_h + (size_t)b * NN * 64;
#pragma unroll
    for (int i = 0; i < 8; i++) {
        int idx = tid + i * 128;
        int row = idx >> 4, c4 = idx & 15;
        *(float4*)&As[row * 68 + c4 * 4] = *(const float4*)&hb[(size_t)(m0 + row) * 64 + c4 * 4];
        *(float4*)&Cs[row * 72 + c4 * 4] = *(const float4*)&g_C[row * 320 + nt * 64 + c4 * 4];
    }
    __syncthreads();

    int warp = tid >> 5, lane = tid & 31, g = lane >> 2, tg = lane & 3;
    int mb = (warp >> 1) * 32, nb = (warp & 1) * 32;
    float acc[2][4][4] = {};
    warptile64<true>(As, 68, Cs, 72, acc, mb, nb, g, tg);

#pragma unroll
    for (int mf = 0; mf < 2; mf++)
#pragma unroll
        for (int nf = 0; nf < 4; nf++) {
            int r0 = mb + mf * 16 + g, c0 = nb + nf * 8 + 2 * tg;
#pragma unroll
            for (int q = 0; q < 4; q++) {
                int lr = r0 + ((q >= 2) ? 8 : 0);
                int cc = c0 + (q & 1);
                float val = acc[mf][nf][q] + g_d[nt * 64 + cc];
                if (nt < 4)
                    g_G[((size_t)b * 4096 + nt * 1024 + m0 + lr) * 64 + cc] = roundtf(val);
                else
                    g_u[((size_t)b * 1024 + m0 + lr) * 64 + cc] = val;  // u kept full fp32
            }
        }
}

// ---------------- kernel 2: big GEMM s = adj @ G with fused gate/h-update epilogue ----------
#define ASZ 4352   // 64*68 floats
#define BSZ 4608   // 64*72 floats
#define STGF 8960  // ASZ+BSZ

__device__ __forceinline__ void load_stage(float* smem, int st, const float* adjb, const float* Gb,
                                           int m0, int kt, int tid) {
    float* As = smem + st * STGF;
    float* Bs = As + ASZ;
    int k0 = kt * 64;
#pragma unroll
    for (int i = 0; i < 8; i++) {
        int idx = tid + i * 128;
        int row = idx >> 4, c4 = idx & 15;
        cpa16(As + row * 68 + c4 * 4, adjb + (size_t)(m0 + row) * 4096 + k0 + c4 * 4);
    }
#pragma unroll
    for (int i = 0; i < 8; i++) {
        int idx = tid + i * 128;
        int row = idx >> 4, c4 = idx & 15;
        cpa16(Bs + row * 72 + c4 * 4, Gb + (size_t)(k0 + row) * 64 + c4 * 4);
    }
}

__global__ __launch_bounds__(128, 2) void step_kernel(const float* __restrict__ adj,
                                                      const float* __restrict__ Wg,
                                                      const float* __restrict__ bgate) {
    extern __shared__ __align__(16) float smem[];
    int tid = threadIdx.x;
    int mt = blockIdx.x, b = blockIdx.y;
    int m0 = mt * 64;
    const float* adjb = adj + (size_t)b * NN * 4096;
    const float* Gb = g_G + (size_t)b * 4096 * 64;

    load_stage(smem, 0, adjb, Gb, m0, 0, tid); CP_COMMIT();
    load_stage(smem, 1, adjb, Gb, m0, 1, tid); CP_COMMIT();

    int warp = tid >> 5, lane = tid & 31, g = lane >> 2, tg = lane & 3;
    int mb = (warp >> 1) * 32, nb = (warp & 1) * 32;
    float acc[2][4][4] = {};

    for (int kt = 0; kt < 64; kt++) {
        CP_WAIT1();
        __syncthreads();
        int st = kt % 3;
        warptile64<true>(smem + st * STGF, 68, smem + st * STGF + ASZ, 72, acc, mb, nb, g, tg);
        __syncthreads();
        if (kt + 2 < 64) load_stage(smem, (kt + 2) % 3, adjb, Gb, m0, kt + 2, tid);
        CP_COMMIT();
    }

    // -------- fused gate epilogue (s lives in acc; never hits gmem) --------
    float* Ws   = smem;               // 64x68  w = z*h (tf32-rounded)
    float* Wg3s = smem + ASZ;         // 64x72  Wg3 (tf32-rounded)
    float* Zs   = smem + STGF;        // 64x68  z stash

#pragma unroll
    for (int i = 0; i < 8; i++) {
        int idx = tid + i * 128;
        int row = idx >> 4, c4 = idx & 15;
        float4 v = *(const float4*)&Wg[(128 + row) * 64 + c4 * 4];
        v.x = roundtf(v.x); v.y = roundtf(v.y); v.z = roundtf(v.z); v.w = roundtf(v.w);
        *(float4*)&Wg3s[row * 72 + c4 * 4] = v;
    }

    float* hb = g_h + (size_t)b * NN * 64;
    const float* ub = g_u + (size_t)b * NN * 64;

#pragma unroll
    for (int mf = 0; mf < 2; mf++)
#pragma unroll
        for (int nf = 0; nf < 4; nf++) {
            int r0 = mb + mf * 16 + g, c0 = nb + nf * 8 + 2 * tg;
#pragma unroll
            for (int q = 0; q < 4; q++) {
                int lr = r0 + ((q >= 2) ? 8 : 0);
                int cc = c0 + (q & 1);
                float uu = ub[(size_t)(m0 + lr) * 64 + cc];
                float hh = hb[(size_t)(m0 + lr) * 64 + cc];
                float pre = acc[mf][nf][q] + uu + bgate[cc];
                float z = 1.f / (1.f + __expf(-pre));
                Zs[lr * 68 + cc] = z;
                Ws[lr * 68 + cc] = roundtf(z * hh);
            }
        }
    __syncthreads();

    float vacc[2][4][4] = {};
    warptile64<false>(Ws, 68, Wg3s, 72, vacc, mb, nb, g, tg);

#pragma unroll
    for (int mf = 0; mf < 2; mf++)
#pragma unroll
        for (int nf = 0; nf < 4; nf++) {
            int r0 = mb + mf * 16 + g, c0 = nb + nf * 8 + 2 * tg;
#pragma unroll
            for (int q = 0; q < 4; q++) {
                int lr = r0 + ((q >= 2) ? 8 : 0);
                int cc = c0 + (q & 1);
                float z = Zs[lr * 68 + cc];
                float hh = hb[(size_t)(m0 + lr) * 64 + cc];
                float ht = tanhf(acc[mf][nf][q] + vacc[mf][nf][q] + bgate[cc]);
                hb[(size_t)(m0 + lr) * 64 + cc] = (1.f - z) * hh + z * ht;
            }
        }
}

// ---------------- kernel 3: final readout ----------------
__global__ __launch_bounds__(256) void final_kernel(const float* __restrict__ ann,
                                                    const float* __restrict__ Wh,
                                                    const float* __restrict__ bh,
                                                    const float* __restrict__ Wo,
                                                    const float* __restrict__ bo,
                                                    float* __restrict__ out) {
    __shared__ float Whs[72 * 64];
    __shared__ float rowbuf[4][72];
    __shared__ float red[4][2];
    int tid = threadIdx.x;
    for (int i = tid; i < 72 * 64; i += 256) Whs[i] = Wh[i];
    int sub = tid >> 6, j = tid & 63;
    int rglob = blockIdx.x * 4 + sub;  // 0..8191 (= b*1024+n)
    rowbuf[sub][j] = g_h[(size_t)rglob * 64 + j];
    if (j < 8) rowbuf[sub][64 + j] = ann[(size_t)rglob * 8 + j];
    __syncthreads();

    float acc = bh[j];
#pragma unroll
    for (int k = 0; k < 72; k++) acc += rowbuf[sub][k] * Whs[k * 64 + j];
    float o = tanhf(acc) * Wo[j];
#pragma unroll
    for (int off = 16; off; off >>= 1) o += __shfl_down_sync(0xffffffffu, o, off);
    if ((tid & 31) == 0) red[sub][j >> 5] = o;
    __syncthreads();
    if (j == 0) out[rglob] = red[sub][0] + red[sub][1] + bo[0];
}

// ---------------- host ----------------
extern "C" void kernel_launch(void* const* d_in, const int* in_sizes, int n_in,
                              void* d_out, int out_size) {
    (void)in_sizes; (void)n_in; (void)out_size;
    const float* init = (const float*)d_in[0];
    const float* ann  = (const float*)d_in[1];
    const float* adj  = (const float*)d_in[2];
    const float* We   = (const float*)d_in[3];
    const float* be   = (const float*)d_in[4];
    const float* Wg   = (const float*)d_in[5];
    const float* bg   = (const float*)d_in[6];
    const float* Wh   = (const float*)d_in[7];
    const float* bh   = (const float*)d_in[8];
    const float* Wo   = (const float*)d_in[9];
    const float* bo   = (const float*)d_in[10];
    float* out = (float*)d_out;

    cudaFuncSetAttribute(step_kernel, cudaFuncAttributeMaxDynamicSharedMemorySize,
                         3 * STGF * (int)sizeof(float));

    cudaMemcpyToSymbolAsync(g_h, init, (size_t)BB * NN * 64 * sizeof(float), 0,
                            cudaMemcpyDeviceToDevice, 0);
    build_C_kernel<<<80, 256>>>(We, be, Wg);
    for (int s = 0; s < NSTEPS; s++) {
        gbuild_kernel<<<dim3(16, 5, BB), 128>>>();
        step_kernel<<<dim3(16, BB), 128, 3 * STGF * sizeof(float)>>>(adj, Wg, bg);
    }
    final_kernel<<<2048, 256>>>(ann, Wh, bh, Wo, bo, out);
}

// round 10
// speedup vs baseline: 1.2953x; 1.2953x over previous
#include <cuda_runtime.h>
#include <cuda_fp16.h>
#include <cstdint>
#include <cstddef>

// GGNN: B=8, N=1024, H=64, E=2, NUM_STEPS=5
// s = adj @ G, G = [h@C_in0; h@C_in1; h@C_out0; h@C_out1] + d  (C = W_edge x W_gate folded)
// z = sigmoid(s + h@Wg3 + bg); h~ = tanh(s + (z*h)@Wg3 + bg); h = (1-z)h + z*h~
// Big GEMM runs in fp16 (same 10-bit mantissa as tf32) with ldmatrix + m16n8k16.

#define NSTEPS 5
#define BB 8
#define NN 1024

// ---------------- scratch (device globals; no allocations allowed) ----------------
__device__ __align__(16) __half g_adjh[(size_t)BB * NN * 4096];  // fp16 copy of adj (64MB)
__device__ float g_C[64 * 320];                    // [C_in0|C_in1|C_out0|C_out1|Wg3], tf32-rounded
__device__ float g_d[320];                         // folded biases (block 4 = 0)
__device__ __align__(16) __half g_Gh[(size_t)BB * 4096 * 64];    // fp16 B operand of big GEMM
__device__ float g_u[(size_t)BB * 1024 * 64];      // u = h @ Wg3 (fp32)
__device__ float g_h[(size_t)BB * 1024 * 64];      // hidden state (in-place updated)

// ---------------- helpers ----------------
__device__ __forceinline__ unsigned f2tf(float x) {
    unsigned r;
    asm("cvt.rna.tf32.f32 %0, %1;" : "=r"(r) : "f"(x));
    return r;
}
__device__ __forceinline__ float roundtf(float x) { return __uint_as_float(f2tf(x)); }

__device__ __forceinline__ void mma8(float c[4], unsigned a0, unsigned a1, unsigned a2, unsigned a3,
                                     unsigned b0, unsigned b1) {
    asm volatile(
        "mma.sync.aligned.m16n8k8.row.col.f32.tf32.tf32.f32 "
        "{%0,%1,%2,%3}, {%4,%5,%6,%7}, {%8,%9}, {%0,%1,%2,%3};"
        : "+f"(c[0]), "+f"(c[1]), "+f"(c[2]), "+f"(c[3])
        : "r"(a0), "r"(a1), "r"(a2), "r"(a3), "r"(b0), "r"(b1));
}

__device__ __forceinline__ void mma16(float c[4], const unsigned a[4], unsigned b0, unsigned b1) {
    asm volatile(
        "mma.sync.aligned.m16n8k16.row.col.f32.f16.f16.f32 "
        "{%0,%1,%2,%3}, {%4,%5,%6,%7}, {%8,%9}, {%0,%1,%2,%3};"
        : "+f"(c[0]), "+f"(c[1]), "+f"(c[2]), "+f"(c[3])
        : "r"(a[0]), "r"(a[1]), "r"(a[2]), "r"(a[3]), "r"(b0), "r"(b1));
}

__device__ __forceinline__ void ldsmx4(unsigned r[4], unsigned sa) {
    asm volatile("ldmatrix.sync.aligned.m8n8.x4.shared.b16 {%0,%1,%2,%3}, [%4];"
                 : "=r"(r[0]), "=r"(r[1]), "=r"(r[2]), "=r"(r[3]) : "r"(sa));
}
__device__ __forceinline__ void ldsmx4t(unsigned r[4], unsigned sa) {
    asm volatile("ldmatrix.sync.aligned.m8n8.x4.trans.shared.b16 {%0,%1,%2,%3}, [%4];"
                 : "=r"(r[0]), "=r"(r[1]), "=r"(r[2]), "=r"(r[3]) : "r"(sa));
}

__device__ __forceinline__ void cpa16(void* smem_dst, const void* gsrc) {
    unsigned s = (unsigned)__cvta_generic_to_shared(smem_dst);
    asm volatile("cp.async.cg.shared.global [%0], [%1], 16;" :: "r"(s), "l"(gsrc) : "memory");
}
#define CP_COMMIT() asm volatile("cp.async.commit_group;" ::: "memory")

// tf32 warp tile (used by gbuild + step epilogue): 32x32 over K=64 from fp32 smem.
template <bool CVTA>
__device__ __forceinline__ void warptile64(const float* As, int lda, const float* Bs, int ldb,
                                           float acc[2][4][4], int mb, int nb, int g, int tg) {
#pragma unroll
    for (int kk = 0; kk < 8; kk++) {
        int k0 = kk * 8;
        unsigned a[2][4];
        unsigned b[4][2];
#pragma unroll
        for (int mf = 0; mf < 2; mf++) {
            const float* ap = As + (mb + mf * 16) * lda + k0;
            float x0 = ap[g * lda + tg];
            float x1 = ap[(g + 8) * lda + tg];
            float x2 = ap[g * lda + tg + 4];
            float x3 = ap[(g + 8) * lda + tg + 4];
            if (CVTA) {
                a[mf][0] = f2tf(x0); a[mf][1] = f2tf(x1);
                a[mf][2] = f2tf(x2); a[mf][3] = f2tf(x3);
            } else {
                a[mf][0] = __float_as_uint(x0); a[mf][1] = __float_as_uint(x1);
                a[mf][2] = __float_as_uint(x2); a[mf][3] = __float_as_uint(x3);
            }
        }
#pragma unroll
        for (int nf = 0; nf < 4; nf++) {
            const float* bp = Bs + k0 * ldb + nb + nf * 8 + g;
            b[nf][0] = __float_as_uint(bp[tg * ldb]);
            b[nf][1] = __float_as_uint(bp[(tg + 4) * ldb]);
        }
#pragma unroll
        for (int mf = 0; mf < 2; mf++)
#pragma unroll
            for (int nf = 0; nf < 4; nf++)
                mma8(acc[mf][nf], a[mf][0], a[mf][1], a[mf][2], a[mf][3], b[nf][0], b[nf][1]);
    }
}

// ---------------- kernel A: adj fp32 -> fp16 (once per launch) ----------------
__global__ __launch_bounds__(256) void conv_kernel(const float4* __restrict__ a) {
    size_t i = (size_t)blockIdx.x * 256 + threadIdx.x;  // 4,194,304 threads, 8 elems each
    float4 v0 = a[2 * i];
    float4 v1 = a[2 * i + 1];
    __half2 p0 = __floats2half2_rn(v0.x, v0.y);
    __half2 p1 = __floats2half2_rn(v0.z, v0.w);
    __half2 p2 = __floats2half2_rn(v1.x, v1.y);
    __half2 p3 = __floats2half2_rn(v1.z, v1.w);
    uint4 o;
    o.x = *(unsigned*)&p0; o.y = *(unsigned*)&p1;
    o.z = *(unsigned*)&p2; o.w = *(unsigned*)&p3;
    ((uint4*)g_adjh)[i] = o;
}

// ---------------- kernel 0: fold W_edge/W_gate into C (64x320) and d (320) ----------------
__global__ void build_C_kernel(const float* __restrict__ We, const float* __restrict__ be,
                               const float* __restrict__ Wg) {
    int idx = blockIdx.x * 256 + threadIdx.x;
    if (idx < 64 * 320) {
        int hp = idx / 320, c = idx % 320;
        int blk = c / 64, j = c % 64;
        float acc;
        if (blk < 4) {
            acc = 0.f;
            int e = blk & 1;
            int go = (blk < 2) ? 0 : 64;
            for (int h = 0; h < 64; h++) acc += We[hp * 128 + 2 * h + e] * Wg[(go + h) * 64 + j];
        } else {
            acc = Wg[(128 + hp) * 64 + j];  // Wg3
        }
        g_C[hp * 320 + c] = roundtf(acc);
    }
    if (idx < 320) {
        int blk = idx / 64, j = idx % 64;
        float acc = 0.f;
        if (blk < 4) {
            int e = blk & 1;
            int go = (blk < 2) ? 0 : 64;
            for (int h = 0; h < 64; h++) acc += be[2 * h + e] * Wg[(go + h) * 64 + j];
        }
        g_d[idx] = acc;
    }
}

// ---------------- kernel 1: G build — h(64-row tile) @ C(64x320), all 5 chunks per CTA ------
#define GB_SMEM (64 * 68 * 4 + 2 * 64 * 72 * 4)  // As + double-buffered C = 54272 B

__global__ __launch_bounds__(128) void gbuild_kernel() {
    extern __shared__ __align__(16) char smraw[];
    float* As = (float*)smraw;            // 64x68
    float* Cs = As + 64 * 68;             // 2 buffers of 64x72
    int tid = threadIdx.x;
    int mt = blockIdx.x, b = blockIdx.y;
    int m0 = mt * 64;
    const float* hb = g_h + (size_t)b * NN * 64;
#pragma unroll
    for (int i = 0; i < 8; i++) {
        int idx = tid + i * 128;
        int row = idx >> 4, c4 = idx & 15;
        *(float4*)&As[row * 68 + c4 * 4] = *(const float4*)&hb[(size_t)(m0 + row) * 64 + c4 * 4];
    }
#pragma unroll
    for (int i = 0; i < 8; i++) {
        int idx = tid + i * 128;
        int row = idx >> 4, c4 = idx & 15;
        cpa16(Cs + row * 72 + c4 * 4, g_C + row * 320 + c4 * 4);
    }
    CP_COMMIT();

    int warp = tid >> 5, lane = tid & 31, g = lane >> 2, tg = lane & 3;
    int mb = (warp >> 1) * 32, nb = (warp & 1) * 32;

    for (int nt = 0; nt < 5; nt++) {
        float* Ccur = Cs + (nt & 1) * (64 * 72);
        if (nt < 4) {
            float* Cnext = Cs + ((nt + 1) & 1) * (64 * 72);
#pragma unroll
            for (int i = 0; i < 8; i++) {
                int idx = tid + i * 128;
                int row = idx >> 4, c4 = idx & 15;
                cpa16(Cnext + row * 72 + c4 * 4, g_C + row * 320 + (nt + 1) * 64 + c4 * 4);
            }
            CP_COMMIT();
            asm volatile("cp.async.wait_group 1;" ::: "memory");
        } else {
            asm volatile("cp.async.wait_group 0;" ::: "memory");
        }
        __syncthreads();

        float acc[2][4][4] = {};
        warptile64<true>(As, 68, Ccur, 72, acc, mb, nb, g, tg);

#pragma unroll
        for (int mf = 0; mf < 2; mf++)
#pragma unroll
            for (int nf = 0; nf < 4; nf++) {
                int r0 = mb + mf * 16 + g, c0 = nb + nf * 8 + 2 * tg;
#pragma unroll
                for (int q = 0; q < 4; q++) {
                    int lr = r0 + ((q >= 2) ? 8 : 0);
                    int cc = c0 + (q & 1);
                    float val = acc[mf][nf][q] + g_d[nt * 64 + cc];
                    if (nt < 4)
                        g_Gh[((size_t)b * 4096 + nt * 1024 + m0 + lr) * 64 + cc] = __float2half_rn(val);
                    else
                        g_u[((size_t)b * 1024 + m0 + lr) * 64 + cc] = val;
                }
            }
        __syncthreads();
    }
}

// ---------------- kernel 2: big fp16 GEMM s = adj @ G with fused gate/h-update ----------
#define STG_HALFS (64 * 72 * 2)               // A(64x72) + B(64x72) halfs = 9216
#define NSTG 5
#define STEP_SMEM (NSTG * STG_HALFS * 2)      // 92160 B

__device__ __forceinline__ void load_stage_h(__half* smem, int st, const __half* adjb,
                                             const __half* Gb, int m0, int kt, int tid) {
    __half* As = smem + st * STG_HALFS;
    __half* Bs = As + 64 * 72;
    int k0 = kt * 64;
#pragma unroll
    for (int i = 0; i < 4; i++) {
        int idx = tid + i * 128;
        int row = idx >> 3, c8 = idx & 7;
        cpa16(As + row * 72 + c8 * 8, adjb + (size_t)(m0 + row) * 4096 + k0 + c8 * 8);
        cpa16(Bs + row * 72 + c8 * 8, Gb + (size_t)(k0 + row) * 64 + c8 * 8);
    }
}

// fp16 warp tile: 32x32 over K=64 via ldmatrix + m16n8k16.
__device__ __forceinline__ void warptile_h(const __half* Ah, const __half* Bh,
                                           float acc[2][4][4], int mb, int nb, int lane) {
    int rowp = lane & 15;
    int colp = (lane >> 4) << 3;  // 0 or 8 (halfs)
    unsigned sA = (unsigned)__cvta_generic_to_shared(Ah);
    unsigned sB = (unsigned)__cvta_generic_to_shared(Bh);
#pragma unroll
    for (int kk = 0; kk < 4; kk++) {
        int k0 = kk * 16;
        unsigned a0[4], a1[4], b0[4], b1[4];
        ldsmx4(a0, sA + (unsigned)(((mb + rowp) * 72) + k0 + colp) * 2u);
        ldsmx4(a1, sA + (unsigned)(((mb + 16 + rowp) * 72) + k0 + colp) * 2u);
        ldsmx4t(b0, sB + (unsigned)(((k0 + rowp) * 72) + nb + colp) * 2u);
        ldsmx4t(b1, sB + (unsigned)(((k0 + rowp) * 72) + nb + 16 + colp) * 2u);
        mma16(acc[0][0], a0, b0[0], b0[1]);
        mma16(acc[0][1], a0, b0[2], b0[3]);
        mma16(acc[0][2], a0, b1[0], b1[1]);
        mma16(acc[0][3], a0, b1[2], b1[3]);
        mma16(acc[1][0], a1, b0[0], b0[1]);
        mma16(acc[1][1], a1, b0[2], b0[3]);
        mma16(acc[1][2], a1, b1[0], b1[1]);
        mma16(acc[1][3], a1, b1[2], b1[3]);
    }
}

__global__ __launch_bounds__(128, 2) void step_kernel(const float* __restrict__ Wg,
                                                      const float* __restrict__ bgate) {
    extern __shared__ __align__(16) char smraw[];
    __half* smh = (__half*)smraw;
    float* smemf = (float*)smraw;
    int tid = threadIdx.x;
    int mt = blockIdx.x, b = blockIdx.y;
    int m0 = mt * 64;
    const __half* adjb = g_adjh + (size_t)b * NN * 4096;
    const __half* Gb = g_Gh + (size_t)b * 4096 * 64;

    load_stage_h(smh, 0, adjb, Gb, m0, 0, tid); CP_COMMIT();
    load_stage_h(smh, 1, adjb, Gb, m0, 1, tid); CP_COMMIT();
    load_stage_h(smh, 2, adjb, Gb, m0, 2, tid); CP_COMMIT();
    load_stage_h(smh, 3, adjb, Gb, m0, 3, tid); CP_COMMIT();

    int warp = tid >> 5, lane = tid & 31, g = lane >> 2, tg = lane & 3;
    int mb = (warp >> 1) * 32, nb = (warp & 1) * 32;
    float acc[2][4][4] = {};

    for (int kt = 0; kt < 64; kt++) {
        asm volatile("cp.async.wait_group 3;" ::: "memory");
        __syncthreads();
        int st = kt % NSTG;
        __half* As = smh + st * STG_HALFS;
        warptile_h(As, As + 64 * 72, acc, mb, nb, lane);
        __syncthreads();
        if (kt + 4 < 64) load_stage_h(smh, (kt + 4) % NSTG, adjb, Gb, m0, kt + 4, tid);
        CP_COMMIT();
    }

    // -------- fused gate epilogue (s lives in acc; never hits gmem) --------
    float* Ws   = smemf;               // 64x68  w = z*h (tf32-rounded)
    float* Wg3s = smemf + 4352;        // 64x72  Wg3 (tf32-rounded)
    float* Zs   = smemf + 8960;        // 64x68  z stash

#pragma unroll
    for (int i = 0; i < 8; i++) {
        int idx = tid + i * 128;
        int row = idx >> 4, c4 = idx & 15;
        float4 v = *(const float4*)&Wg[(128 + row) * 64 + c4 * 4];
        v.x = roundtf(v.x); v.y = roundtf(v.y); v.z = roundtf(v.z); v.w = roundtf(v.w);
        *(float4*)&Wg3s[row * 72 + c4 * 4] = v;
    }

    float* hb = g_h + (size_t)b * NN * 64;
    const float* ub = g_u + (size_t)b * NN * 64;

#pragma unroll
    for (int mf = 0; mf < 2; mf++)
#pragma unroll
        for (int nf = 0; nf < 4; nf++) {
            int r0 = mb + mf * 16 + g, c0 = nb + nf * 8 + 2 * tg;
#pragma unroll
            for (int q = 0; q < 4; q++) {
                int lr = r0 + ((q >= 2) ? 8 : 0);
                int cc = c0 + (q & 1);
                float uu = ub[(size_t)(m0 + lr) * 64 + cc];
                float hh = hb[(size_t)(m0 + lr) * 64 + cc];
                float pre = acc[mf][nf][q] + uu + bgate[cc];
                float z = 1.f / (1.f + __expf(-pre));
                Zs[lr * 68 + cc] = z;
                Ws[lr * 68 + cc] = roundtf(z * hh);
            }
        }
    __syncthreads();

    float vacc[2][4][4] = {};
    warptile64<false>(Ws, 68, Wg3s, 72, vacc, mb, nb, g, tg);

#pragma unroll
    for (int mf = 0; mf < 2; mf++)
#pragma unroll
        for (int nf = 0; nf < 4; nf++) {
            int r0 = mb + mf * 16 + g, c0 = nb + nf * 8 + 2 * tg;
#pragma unroll
            for (int q = 0; q < 4; q++) {
                int lr = r0 + ((q >= 2) ? 8 : 0);
                int cc = c0 + (q & 1);
                float z = Zs[lr * 68 + cc];
                float hh = hb[(size_t)(m0 + lr) * 64 + cc];
                float ht = tanhf(acc[mf][nf][q] + vacc[mf][nf][q] + bgate[cc]);
                hb[(size_t)(m0 + lr) * 64 + cc] = (1.f - z) * hh + z * ht;
            }
        }
}

// ---------------- kernel 3: final readout ----------------
__global__ __launch_bounds__(256) void final_kernel(const float* __restrict__ ann,
                                                    const float* __restrict__ Wh,
                                                    const float* __restrict__ bh,
                                                    const float* __restrict__ Wo,
                                                    const float* __restrict__ bo,
                                                    float* __restrict__ out) {
    __shared__ float Whs[72 * 64];
    __shared__ float rowbuf[4][72];
    __shared__ float red[4][2];
    int tid = threadIdx.x;
    for (int i = tid; i < 72 * 64; i += 256) Whs[i] = Wh[i];
    int sub = tid >> 6, j = tid & 63;
    int rglob = blockIdx.x * 4 + sub;  // 0..8191 (= b*1024+n)
    rowbuf[sub][j] = g_h[(size_t)rglob * 64 + j];
    if (j < 8) rowbuf[sub][64 + j] = ann[(size_t)rglob * 8 + j];
    __syncthreads();

    float acc = bh[j];
#pragma unroll
    for (int k = 0; k < 72; k++) acc += rowbuf[sub][k] * Whs[k * 64 + j];
    float o = tanhf(acc) * Wo[j];
#pragma unroll
    for (int off = 16; off; off >>= 1) o += __shfl_down_sync(0xffffffffu, o, off);
    if ((tid & 31) == 0) red[sub][j >> 5] = o;
    __syncthreads();
    if (j == 0) out[rglob] = red[sub][0] + red[sub][1] + bo[0];
}

// ---------------- host ----------------
extern "C" void kernel_launch(void* const* d_in, const int* in_sizes, int n_in,
                              void* d_out, int out_size) {
    (void)in_sizes; (void)n_in; (void)out_size;
    const float* init = (const float*)d_in[0];
    const float* ann  = (const float*)d_in[1];
    const float* adj  = (const float*)d_in[2];
    const float* We   = (const float*)d_in[3];
    const float* be   = (const float*)d_in[4];
    const float* Wg   = (const float*)d_in[5];
    const float* bg   = (const float*)d_in[6];
    const float* Wh   = (const float*)d_in[7];
    const float* bh   = (const float*)d_in[8];
    const float* Wo   = (const float*)d_in[9];
    const float* bo   = (const float*)d_in[10];
    float* out = (float*)d_out;

    cudaFuncSetAttribute(step_kernel, cudaFuncAttributeMaxDynamicSharedMemorySize, STEP_SMEM);
    cudaFuncSetAttribute(gbuild_kernel, cudaFuncAttributeMaxDynamicSharedMemorySize, GB_SMEM);

    cudaMemcpyToSymbolAsync(g_h, init, (size_t)BB * NN * 64 * sizeof(float), 0,
                            cudaMemcpyDeviceToDevice, 0);
    conv_kernel<<<16384, 256>>>((const float4*)adj);
    build_C_kernel<<<80, 256>>>(We, be, Wg);
    for (int s = 0; s < NSTEPS; s++) {
        gbuild_kernel<<<dim3(16, BB), 128, GB_SMEM>>>();
        step_kernel<<<dim3(16, BB), 128, STEP_SMEM>>>(Wg, bg);
    }
    final_kernel<<<2048, 256>>>(ann, Wh, bh, Wo, bo, out);
}